// round 14
// baseline (speedup 1.0000x reference)
#include <cuda_runtime.h>
#include <cstdint>

#define POOL 14
#define IMG_H 200
#define IMG_W 200
#define IMG_C 1024
#define NUM_ROIS 512
#define NUM_CELLS (NUM_ROIS * POOL * POOL)   // 100352

#define NCHUNK 4                       // 256-ch slices -> 41MB image slice, L2-resident
#define CHUNK_FLOATS (IMG_C / NCHUNK)  // 256 floats per cell-chunk
#define WARPS_PER_BLOCK 8
#define THREADS (WARPS_PER_BLOCK * 32) // 256

typedef unsigned long long u64;

// Per-cell precomputed parameters: 4 corner base pointers (chunk 0) +
// 4 pre-packed f32x2 weights. Exactly 64B.
struct __align__(16) CellParams {
    u64 p00, p01, p10, p11;        // corner base addresses (as integers)
    u64 wx2, omwx2, wy2, omwy2;    // packed {w,w} f32x2 weights
};
__device__ CellParams g_params[NUM_CELLS];   // 6.4 MB device scratch

// ---- packed f32x2 helpers (sm_103a) ----
__device__ __forceinline__ u64 pk2(float a, float b) {
    u64 r;
    asm("mov.b64 %0, {%1, %2};" : "=l"(r) : "f"(a), "f"(b));
    return r;
}
__device__ __forceinline__ u64 mul2(u64 a, u64 b) {
    u64 r;
    asm("mul.rn.f32x2 %0, %1, %2;" : "=l"(r) : "l"(a), "l"(b));
    return r;
}
__device__ __forceinline__ u64 fma2(u64 a, u64 b, u64 c) {
    u64 r;
    asm("fma.rn.f32x2 %0, %1, %2, %3;" : "=l"(r) : "l"(a), "l"(b), "l"(c));
    return r;
}

// 256-bit L2-only gather load (no L1 allocation; gathers have ~no L1 reuse).
__device__ __forceinline__ void ldg256_cg(u64 addr,
                                          u64& r0, u64& r1, u64& r2, u64& r3) {
    asm volatile("ld.global.cg.v4.b64 {%0,%1,%2,%3}, [%4];"
                 : "=l"(r0), "=l"(r1), "=l"(r2), "=l"(r3) : "l"(addr));
}

// 256-bit streaming store (evict-first: protects the L2-resident image slice).
__device__ __forceinline__ void stg256_cs(float* p, u64 r0, u64 r1, u64 r2, u64 r3) {
    asm volatile("st.global.cs.v4.b64 [%0], {%1,%2,%3,%4};"
                 :: "l"(p), "l"(r0), "l"(r1), "l"(r2), "l"(r3) : "memory");
}

// ---------------- Prologue: per-cell setup, computed once ----------------
__global__ void precompute_params(const float* __restrict__ img,
                                  const int* __restrict__ rois)
{
    const int idx = blockIdx.x * blockDim.x + threadIdx.x;
    if (idx >= NUM_CELLS) return;

    const int roi  = idx / (POOL * POOL);
    const int cell = idx - roi * (POOL * POOL);
    const int py   = cell / POOL;
    const int px   = cell - py * POOL;

    const int4 box = reinterpret_cast<const int4*>(rois)[roi];
    const int bx = box.x, by = box.y, bw = box.z, bh = box.w;

    // Match reference math: fraction from UNclipped floor.
    const float sy = (float)py * ((float)bh / (float)POOL);
    const float sx = (float)px * ((float)bw / (float)POOL);
    const int y0 = (int)floorf(sy);
    const int x0 = (int)floorf(sx);
    const float wy = sy - (float)y0;
    const float wx = sx - (float)x0;

    const int y0c = min(max(y0, 0), bh - 1);
    const int y1c = min(max(y0 + 1, 0), bh - 1);
    const int x0c = min(max(x0, 0), bw - 1);
    const int x1c = min(max(x0 + 1, 0), bw - 1);

    const int iy0 = by + y0c;
    const int iy1 = by + y1c;
    const int ix0 = bx + x0c;
    const int ix1 = bx + x1c;

    CellParams cp;
    cp.p00 = (u64)(img + ((size_t)iy0 * IMG_W + ix0) * IMG_C);
    cp.p01 = (u64)(img + ((size_t)iy0 * IMG_W + ix1) * IMG_C);
    cp.p10 = (u64)(img + ((size_t)iy1 * IMG_W + ix0) * IMG_C);
    cp.p11 = (u64)(img + ((size_t)iy1 * IMG_W + ix1) * IMG_C);
    cp.wx2   = pk2(wx, wx);
    cp.omwx2 = pk2(1.0f - wx, 1.0f - wx);
    cp.wy2   = pk2(wy, wy);
    cp.omwy2 = pk2(1.0f - wy, 1.0f - wy);
    g_params[idx] = cp;
}

// ---------------- Main: warp-per-cell-chunk, setup-free ----------------
// grid = (cells/8, NCHUNK). Chunk-outer keeps each 41MB channel slice
// L2-resident (~472MB DRAM). Per warp: 4 uniform param loads + <=4 LDG.256.cg
// + 12 packed FMAs + 1 STG.256.cs for 1KB of output (~30 instrs/KB vs R13's 60).
__global__ void __launch_bounds__(THREADS, 6)
roi_resize_main(float* __restrict__ out)
{
    const int warp = threadIdx.x >> 5;
    const int lane = threadIdx.x & 31;

    const int idx = blockIdx.x * WARPS_PER_BLOCK + warp;   // cell id
    const int chunk_off = blockIdx.y * CHUNK_FLOATS;

    // Uniform (broadcast) param loads: 4x 16B.
    const u64* q = reinterpret_cast<const u64*>(&g_params[idx]);
    u64 p00, p01, p10, p11, wx2, omwx2, wy2, omwy2;
    asm("ld.global.nc.v2.b64 {%0,%1}, [%2];"      : "=l"(p00), "=l"(p01)     : "l"(q));
    asm("ld.global.nc.v2.b64 {%0,%1}, [%2+16];"   : "=l"(p10), "=l"(p11)     : "l"(q));
    asm("ld.global.nc.v2.b64 {%0,%1}, [%2+32];"   : "=l"(wx2), "=l"(omwx2)   : "l"(q));
    asm("ld.global.nc.v2.b64 {%0,%1}, [%2+48];"   : "=l"(wy2), "=l"(omwy2)   : "l"(q));

    // Warp-uniform zero-weight flags (wx2 packs {wx,wx}; zero iff wx==+0.f).
    const bool need_x1 = (wx2 != 0ull);
    const bool need_y1 = (wy2 != 0ull);

    const u64 boff = (u64)(chunk_off + lane * 8) * 4u;   // byte offset into each corner row

    u64 g00a, g00b, g00c, g00d;
    ldg256_cg(p00 + boff, g00a, g00b, g00c, g00d);

    u64 g01a = 0, g01b = 0, g01c = 0, g01d = 0;
    if (need_x1) ldg256_cg(p01 + boff, g01a, g01b, g01c, g01d);

    u64 g10a = 0, g10b = 0, g10c = 0, g10d = 0;
    u64 g11a = 0, g11b = 0, g11c = 0, g11d = 0;
    if (need_y1) {
        ldg256_cg(p10 + boff, g10a, g10b, g10c, g10d);
        if (need_x1) ldg256_cg(p11 + boff, g11a, g11b, g11c, g11d);
    }

#define XLERP(g0, g1) fma2(g1, wx2, mul2(g0, omwx2))

    const u64 ta = need_x1 ? XLERP(g00a, g01a) : g00a;
    const u64 tb = need_x1 ? XLERP(g00b, g01b) : g00b;
    const u64 tc = need_x1 ? XLERP(g00c, g01c) : g00c;
    const u64 td = need_x1 ? XLERP(g00d, g01d) : g00d;

    const u64 ba = need_y1 ? (need_x1 ? XLERP(g10a, g11a) : g10a) : ta;
    const u64 bb = need_y1 ? (need_x1 ? XLERP(g10b, g11b) : g10b) : tb;
    const u64 bc = need_y1 ? (need_x1 ? XLERP(g10c, g11c) : g10c) : tc;
    const u64 bd = need_y1 ? (need_x1 ? XLERP(g10d, g11d) : g10d) : td;

    const u64 r0 = fma2(ba, wy2, mul2(ta, omwy2));
    const u64 r1 = fma2(bb, wy2, mul2(tb, omwy2));
    const u64 r2 = fma2(bc, wy2, mul2(tc, omwy2));
    const u64 r3 = fma2(bd, wy2, mul2(td, omwy2));
#undef XLERP

    float* o = out + (size_t)idx * IMG_C + chunk_off + lane * 8;
    stg256_cs(o, r0, r1, r2, r3);
}

extern "C" void kernel_launch(void* const* d_in, const int* in_sizes, int n_in,
                              void* d_out, int out_size)
{
    const float* img  = (const float*)d_in[0];
    const int*   rois = (const int*)d_in[1];
    if (in_sizes[0] == NUM_ROIS * 4) {  // defensive: swapped order
        rois = (const int*)d_in[0];
        img  = (const float*)d_in[1];
    }
    float* out = (float*)d_out;

    precompute_params<<<(NUM_CELLS + 255) / 256, 256>>>(img, rois);

    dim3 grid(NUM_CELLS / WARPS_PER_BLOCK, NCHUNK);  // (12544, 4)
    roi_resize_main<<<grid, THREADS>>>(out);
}

// round 15
// speedup vs baseline: 1.8201x; 1.8201x over previous
#include <cuda_runtime.h>
#include <cstdint>

#define POOL 14
#define IMG_H 200
#define IMG_W 200
#define IMG_C 1024
#define NUM_ROIS 512

#define NCHUNK 4                       // 256-ch slices -> 41MB image slice, L2-resident
#define CHUNK_FLOATS (IMG_C / NCHUNK)  // 256 floats per cell-chunk
#define LANES_PER_CELL 16
#define CELLS_PER_BLOCK 16
#define THREADS (LANES_PER_CELL * CELLS_PER_BLOCK)  // 256

typedef unsigned long long u64;

// ---- packed f32x2 helpers (sm_103a) ----
__device__ __forceinline__ u64 pk2(float a, float b) {
    u64 r;
    asm("mov.b64 %0, {%1, %2};" : "=l"(r) : "f"(a), "f"(b));
    return r;
}
__device__ __forceinline__ u64 mul2(u64 a, u64 b) {
    u64 r;
    asm("mul.rn.f32x2 %0, %1, %2;" : "=l"(r) : "l"(a), "l"(b));
    return r;
}
__device__ __forceinline__ u64 fma2(u64 a, u64 b, u64 c) {
    u64 r;
    asm("fma.rn.f32x2 %0, %1, %2, %3;" : "=l"(r) : "l"(a), "l"(b), "l"(c));
    return r;
}

// 128-bit L2-only load (no L1 allocation; gathers have ~no L1 reuse).
__device__ __forceinline__ void ldg128_cg(const float* p, u64& lo, u64& hi) {
    asm volatile("ld.global.cg.v2.b64 {%0,%1}, [%2];" : "=l"(lo), "=l"(hi) : "l"(p));
}

// 128-bit streaming store (evict-first: protects the L2-resident image slice).
__device__ __forceinline__ void stg128_cs(float* p, u64 lo, u64 hi) {
    asm volatile("st.global.cs.v2.b64 [%0], {%1,%2};" :: "l"(p), "l"(lo), "l"(hi) : "memory");
}

// R12 winner + two edits:
//  1. Zero-select removal: when wx==+0 (or wy==+0) the skipped corner regs
//     stay 0 and the UNCONDITIONAL packed-lerp chain is still exact
//     (0*0 + g*1 == g in IEEE). Guarded loads keep the traffic saving;
//     the ~16 predicated selects per batch are gone.
//  2. launch_bounds(256,6): reg cap 42 -> 6 CTAs/SM (was 5 at 48 regs).
__global__ void __launch_bounds__(THREADS, 6)
roi_resize_kernel(const float* __restrict__ img,
                  const int* __restrict__ rois,
                  float* __restrict__ out)
{
    const int cell_local = threadIdx.x >> 4;        // 0..15
    const int c          = threadIdx.x & 15;        // float4 lane within cell

    const int idx  = blockIdx.x * CELLS_PER_BLOCK + cell_local;  // 0..100351
    const int roi  = idx / (POOL * POOL);
    const int cell = idx - roi * (POOL * POOL);
    const int py   = cell / POOL;
    const int px   = cell - py * POOL;

    const int chunk_off = blockIdx.y * CHUNK_FLOATS;

    const int4 box = reinterpret_cast<const int4*>(rois)[roi];
    const int bx = box.x, by = box.y, bw = box.z, bh = box.w;

    // Match reference math: fraction from UNclipped floor.
    const float sy = (float)py * ((float)bh / (float)POOL);
    const float sx = (float)px * ((float)bw / (float)POOL);
    const int y0 = (int)floorf(sy);
    const int x0 = (int)floorf(sx);
    const float wy = sy - (float)y0;
    const float wx = sx - (float)x0;

    const bool need_x1 = (wx != 0.0f);   // right corners carry weight
    const bool need_y1 = (wy != 0.0f);   // bottom corners carry weight
    const bool need_xy = need_x1 && need_y1;

    const int y0c = min(max(y0, 0), bh - 1);
    const int y1c = min(max(y0 + 1, 0), bh - 1);
    const int x0c = min(max(x0, 0), bw - 1);
    const int x1c = min(max(x0 + 1, 0), bw - 1);

    const int iy0 = by + y0c;
    const int iy1 = by + y1c;
    const int ix0 = bx + x0c;
    const int ix1 = bx + x1c;

    const u64 wx2   = pk2(wx, wx);
    const u64 omwx2 = pk2(1.0f - wx, 1.0f - wx);
    const u64 wy2   = pk2(wy, wy);
    const u64 omwy2 = pk2(1.0f - wy, 1.0f - wy);

    const float* base = img + chunk_off;
    const float* __restrict__ p00 = base + ((size_t)iy0 * IMG_W + ix0) * IMG_C;
    const float* __restrict__ p01 = base + ((size_t)iy0 * IMG_W + ix1) * IMG_C;
    const float* __restrict__ p10 = base + ((size_t)iy1 * IMG_W + ix0) * IMG_C;
    const float* __restrict__ p11 = base + ((size_t)iy1 * IMG_W + ix1) * IMG_C;

    float* __restrict__ o = out + (size_t)idx * IMG_C + chunk_off;

    // x-lerp of one packed pair; safe for skipped corners (regs==0, weight==0).
#define XLERP(g0, g1) fma2(g1, wx2, mul2(g0, omwx2))

    // Two batches (R5/R12 structure): each covers float offsets
    // [f0, f0+16) and [f1, f1+16); up to 8 front-batched 128-bit loads.
#pragma unroll
    for (int h = 0; h < 2; h++) {
        const int f0 = (c + h * 32) * 4;
        const int f1 = f0 + 64;

        u64 a00l, a00h, b00l, b00h;
        ldg128_cg(p00 + f0, a00l, a00h);
        ldg128_cg(p00 + f1, b00l, b00h);

        u64 a01l = 0, a01h = 0, b01l = 0, b01h = 0;
        if (need_x1) {
            ldg128_cg(p01 + f0, a01l, a01h);
            ldg128_cg(p01 + f1, b01l, b01h);
        }
        u64 a10l = 0, a10h = 0, b10l = 0, b10h = 0;
        if (need_y1) {
            ldg128_cg(p10 + f0, a10l, a10h);
            ldg128_cg(p10 + f1, b10l, b10h);
        }
        u64 a11l = 0, a11h = 0, b11l = 0, b11h = 0;
        if (need_xy) {
            ldg128_cg(p11 + f0, a11l, a11h);
            ldg128_cg(p11 + f1, b11l, b11h);
        }

        // Unconditional lerp chain — exact even for skipped corners:
        // wx==+0 ==> XLERP(g0, anything) == g0; wy==+0 ==> r == top.
        const u64 tal = XLERP(a00l, a01l);
        const u64 tah = XLERP(a00h, a01h);
        const u64 tbl = XLERP(b00l, b01l);
        const u64 tbh = XLERP(b00h, b01h);

        const u64 bal = XLERP(a10l, a11l);
        const u64 bah = XLERP(a10h, a11h);
        const u64 bbl = XLERP(b10l, b11l);
        const u64 bbh = XLERP(b10h, b11h);

        const u64 ral = fma2(bal, wy2, mul2(tal, omwy2));
        const u64 rah = fma2(bah, wy2, mul2(tah, omwy2));
        const u64 rbl = fma2(bbl, wy2, mul2(tbl, omwy2));
        const u64 rbh = fma2(bbh, wy2, mul2(tbh, omwy2));

        stg128_cs(o + f0, ral, rah);
        stg128_cs(o + f1, rbl, rbh);
    }
#undef XLERP
}

extern "C" void kernel_launch(void* const* d_in, const int* in_sizes, int n_in,
                              void* d_out, int out_size)
{
    const float* img  = (const float*)d_in[0];
    const int*   rois = (const int*)d_in[1];
    if (in_sizes[0] == NUM_ROIS * 4) {  // defensive: swapped order
        rois = (const int*)d_in[0];
        img  = (const float*)d_in[1];
    }
    float* out = (float*)d_out;

    dim3 grid((NUM_ROIS * POOL * POOL) / CELLS_PER_BLOCK, NCHUNK);  // (6272, 4)
    roi_resize_kernel<<<grid, THREADS>>>(img, rois, out);
}